// round 6
// baseline (speedup 1.0000x reference)
#include <cuda_runtime.h>
#include <cstddef>

// ManyBodyVoxel: out[0, a, c=t*2+l, x, y, z] =
//   sum_n exp(coeff * || grid_l[x,y,z] - d[a,n]*mask_t[a,n] ||^2)
// Separable Gaussian -> rank-1 outer products of per-(atom,axis) exp rows.
// Non-matching atoms contribute the d=0 base Gaussian.
// R6: classify FIRST (ballot prefix -> compact order), build exp-table records
//     IN CLASSIFIED ORDER so the consumer walks contiguous 256B records with
//     ptr += 256 -- no list indirection, no branches, no manual pipelining.

#define NT 1024

typedef unsigned long long u64;

__device__ __forceinline__ u64 pk2(float v) {
    u64 r; asm("mov.b64 %0, {%1, %2};" : "=l"(r) : "f"(v), "f"(v)); return r;
}
__device__ __forceinline__ u64 fma2(u64 a, u64 b, u64 c) {
    u64 d; asm("fma.rn.f32x2 %0, %1, %2, %3;" : "=l"(d) : "l"(a), "l"(b), "l"(c)); return d;
}
__device__ __forceinline__ u64 mul2(u64 a, u64 b) {
    u64 d; asm("mul.rn.f32x2 %0, %1, %2;" : "=l"(d) : "l"(a), "l"(b)); return d;
}

__global__ __launch_bounds__(NT, 1)
void mbv_kernel(const float* __restrict__ dist,   // (1,128,64,3) fp32
                const float* __restrict__ sigma,  // (1,) fp32
                const int*   __restrict__ anum,   // (128,64) int64 or int32 (auto-detect)
                float* __restrict__ out)          // (1,128,10,16,16,16) fp32
{
    const int a   = blockIdx.x;
    const int tid = threadIdx.x;
    const int zh  = tid & 1;          // z half: [zh*8, zh*8+8)
    const int y   = (tid >> 1) & 15;
    const int x   = (tid >> 5) & 15;
    const int l   = tid >> 9;         // 0: L=8, 1: L=12

    // Record (l, slot): 64 floats = 256B.  x @ +0, y @ +64B, z @ +128B, pad.
    // Slots 0..ncls-1: classified atoms in type-major compact order; slot 64: base (d=0).
    __shared__ __align__(16) float tab[2 * 65 * 64];
    __shared__ float dsm[192];        // staged dist row (64 atoms x 3)
    __shared__ short ord[64];         // compact slot -> atom index
    __shared__ int   startc[5];       // prefix starts per type
    __shared__ int   cntc[5];
    __shared__ int   nclss;

    const float s  = sigma[0];
    const float cf = -0.5f / (s * s);

    // ---- Phase 0 (parallel): warp0 classifies; threads 64..255 stage dist ----
    if (tid < 32) {
        // Independent LDGs: probe row 0 + both dtype interpretations of row a.
        int4 p = ((const int4*)anum)[tid];
        int4 q = ((const int4*)anum)[a * 32 + tid];   // int64 view
        int2 r = ((const int2*)anum)[a * 32 + tid];   // int32 view
        bool i32 = __any_sync(0xffffffffu, (p.y | p.w) != 0);
        int z0 = i32 ? r.x : q.x;     // atom 2*tid
        int z1 = i32 ? r.y : q.z;     // atom 2*tid+1
        unsigned lt = (1u << tid) - 1u;
        const int ZT[5] = {1, 6, 7, 8, 16};
        int base = 0;
        #pragma unroll
        for (int t = 0; t < 5; t++) {
            unsigned m0 = __ballot_sync(0xffffffffu, z0 == ZT[t]);
            unsigned m1 = __ballot_sync(0xffffffffu, z1 == ZT[t]);
            int c0 = __popc(m0), c = c0 + __popc(m1);
            if (z0 == ZT[t]) ord[base + __popc(m0 & lt)]      = (short)(2 * tid);
            if (z1 == ZT[t]) ord[base + c0 + __popc(m1 & lt)] = (short)(2 * tid + 1);
            if (tid == 0) { startc[t] = base; cntc[t] = c; }
            base += c;
        }
        if (tid == 0) nclss = base;
    } else if (tid < 256) {
        dsm[tid - 64] = dist[a * 192 + (tid - 64)];
    }

    __syncthreads();

    // ---- Phase 1: exp tables in classified order ----
    {
        const int nrec = nclss + 1;           // + base record
        const int lp = tid & 1;
        const int u  = tid >> 1;              // unit: (slot, ax, jhalf)
        if (u < 6 * nrec) {
            int slot = u / 6;
            int rem  = u - slot * 6;
            int ax   = rem >> 1;
            int jh   = rem & 1;
            int isbase = (slot == nclss);
            int recid  = isbase ? 64 : slot;
            float dv   = isbase ? 0.0f : dsm[ord[slot] * 3 + ax];
            float Lp   = lp ? 12.0f : 8.0f;
            float half = 0.5f * Lp;
            float step = Lp * (1.0f / 15.0f);
            float* dst = &tab[(lp * 65 + recid) * 64 + ax * 16 + jh * 8];
            float bse  = -half - dv + step * (float)(jh * 8);
            #pragma unroll
            for (int j = 0; j < 8; j++) {
                float uu = bse + step * (float)j;
                dst[j] = __expf(cf * uu * uu);
            }
        }
    }

    __syncthreads();

    // ---- Phase 2: consumer. Thread owns 8 voxels of column (l, x, y) ----
    const char* tb = reinterpret_cast<const char*>(tab) + l * (65 * 256);
    const int offx = x * 4;
    const int offy = 64 + y * 4;
    const int offz = 128 + zh * 32;

    const char* br = tb + 64 * 256;   // base record
    const float bxy = *(const float*)(br + offx) * *(const float*)(br + offy);
    const ulonglong2 bqa = *(const ulonglong2*)(br + offz);
    const ulonglong2 bqb = *(const ulonglong2*)(br + offz + 16);
    const u64 Pxy = pk2(bxy);
    const u64 B0 = mul2(Pxy, bqa.x), B1 = mul2(Pxy, bqa.y);
    const u64 B2 = mul2(Pxy, bqb.x), B3 = mul2(Pxy, bqb.y);

    char* op = reinterpret_cast<char*>(out)
             + ((((size_t)(a * 10 + l)) << 12) + ((size_t)x << 8) + ((size_t)y << 4) + ((size_t)zh << 3)) * 4;

    #pragma unroll
    for (int t = 0; t < 5; t++) {
        const int c = cntc[t];
        const u64 bm = pk2((float)(64 - c));
        u64 a0 = mul2(bm, B0), a1 = mul2(bm, B1), a2 = mul2(bm, B2), a3 = mul2(bm, B3);

        const char* p = tb + startc[t] * 256;
        #pragma unroll 2
        for (int k = 0; k < c; k++) {
            float sx = *(const float*)(p + offx);
            float sy = *(const float*)(p + offy);
            ulonglong2 qa = *(const ulonglong2*)(p + offz);
            ulonglong2 qb = *(const ulonglong2*)(p + offz + 16);
            u64 sp = pk2(sx * sy);
            a0 = fma2(sp, qa.x, a0);
            a1 = fma2(sp, qa.y, a1);
            a2 = fma2(sp, qb.x, a2);
            a3 = fma2(sp, qb.y, a3);
            p += 256;
        }

        __stcs((ulonglong2*)op,        make_ulonglong2(a0, a1));
        __stcs((ulonglong2*)(op + 16), make_ulonglong2(a2, a3));
        op += 2 * 4096 * 4;   // next type channel
    }
}

extern "C" void kernel_launch(void* const* d_in, const int* in_sizes, int n_in,
                              void* d_out, int out_size) {
    const float* dist = nullptr;
    const float* sig  = nullptr;
    const int*   an   = nullptr;
    for (int i = 0; i < n_in; i++) {
        if (in_sizes[i] == 1)          sig  = (const float*)d_in[i];
        else if (in_sizes[i] == 24576) dist = (const float*)d_in[i];
        else if (in_sizes[i] == 8192)  an   = (const int*)d_in[i];
    }
    if (!dist) dist = (const float*)d_in[0];
    if (!sig)  sig  = (const float*)d_in[1];
    if (!an)   an   = (const int*)d_in[2];

    mbv_kernel<<<128, NT>>>(dist, sig, an, (float*)d_out);
}